// round 2
// baseline (speedup 1.0000x reference)
#include <cuda_runtime.h>

// QualityAwarePatchAugment — GB300 sm_103a
// B=32, C=1, H=W=1024, PS=16 -> 64x64 = 4096 patches.
// Two-phase: (A) per-patch stats -> action code/param/m_pp, (B) apply.
//
// R2: exploit cross-launch L2 residency. img (128 MB) ~fits in L2 (126 MB);
// stats deposits it with default .ca loads, apply re-reads it as L2 hits.
// Output stores + noise loads use streaming (.cs) policy so they don't evict
// the img lines.

#define NPATCH 4096

// Packed per-patch metadata: x=code(as int bits), y=param, z=m_pp
__device__ float4 g_meta[NPATCH];

__device__ __forceinline__ float clipf(float v) {
    return fminf(fmaxf(v, 0.0f), 1.0f);
}

// ---------------------------------------------------------------------------
// Kernel A: per-patch statistics + action code.
// grid = 4096 (one block per patch), block = 256 threads.
// ---------------------------------------------------------------------------
__global__ void __launch_bounds__(256) stats_kernel(
    const float4* __restrict__ img,
    const float*  __restrict__ r_strong,
    const float*  __restrict__ r_drop,
    const float*  __restrict__ r_else,
    const float*  __restrict__ bright_f,
    const float*  __restrict__ contrast_f,
    const float*  __restrict__ slight_f,
    const int*    __restrict__ aug_choice,
    const int*    __restrict__ slight_choice)
{
    const int p  = blockIdx.x;          // patch linear index, ph*64+pw
    const int ph = p >> 6;
    const int pw = p & 63;
    const int t  = threadIdx.x;
    const int b  = t >> 3;              // batch 0..31
    const int l8 = t & 7;               // 8 threads per batch

    // pixel base of this (batch, patch): (b, ph*16, pw*16)
    const int pixbase = (b << 20) + ((ph << 4) << 10) + (pw << 4);
    const int f4base  = pixbase >> 2;   // float4 index; row stride = 256 f4

    float s = 0.0f, s2 = 0.0f;
    #pragma unroll
    for (int k = 0; k < 8; k++) {
        const int fi  = l8 + (k << 3);  // float4 slot within patch, 0..63
        const int row = fi >> 2;
        const int c4  = fi & 3;
        // default .ca load: deposit img into L2 for the apply kernel
        const float4 v = img[f4base + (row << 8) + c4];
        s  += v.x + v.y + v.z + v.w;
        s2 += v.x * v.x + v.y * v.y + v.z * v.z + v.w * v.w;
    }
    // width-8 reduce (threads of one batch are 8 consecutive lanes)
    #pragma unroll
    for (int off = 4; off; off >>= 1) {
        s  += __shfl_down_sync(0xffffffffu, s,  off, 8);
        s2 += __shfl_down_sync(0xffffffffu, s2, off, 8);
    }

    __shared__ float sh_s[32], sh_s2[32];
    if (l8 == 0) { sh_s[b] = s; sh_s2[b] = s2; }
    __syncthreads();

    if (t < 32) {
        const float bs  = sh_s[t];
        const float bs2 = sh_s2[t];
        const float mean = bs * (1.0f / 256.0f);
        float var = (bs2 - bs * bs * (1.0f / 256.0f)) * (1.0f / 255.0f); // ddof=1
        var = fmaxf(var, 0.0f);
        const float sd   = sqrtf(var);
        const float iq   = 1.0f - 2.0f * fabsf(mean - 0.5f);
        const float qual = (sd + iq + var) * (1.0f / 3.0f);

        float qs  = qual;   // batch-sum of quality
        float tot = bs;     // batch-sum of pixel sum (for m_pp)
        #pragma unroll
        for (int off = 16; off; off >>= 1) {
            qs  += __shfl_down_sync(0xffffffffu, qs,  off);
            tot += __shfl_down_sync(0xffffffffu, tot, off);
        }
        if (t == 0) {
            const float q   = qs  * (1.0f / 32.0f);
            const float mpp = tot * (1.0f / 8192.0f);   // 32 batches * 256 px

            const bool low    = q < 0.7f;
            const bool strong = low && (r_strong[p] < 0.8f);
            const bool drop   = low && (q < 0.3f) && (r_drop[p] < 0.1f);
            const bool els    = (!low) && (r_else[p] < 0.3f);

            int code = 0;
            if (strong) code = aug_choice[p] + 1;       // 1..4
            if (els)    code = slight_choice[p] + 5;    // 5..6
            if (drop)   code = 7;

            float param = 0.0f;
            switch (code) {
                case 1: param = 0.1f;          break;   // noise scale
                case 3: param = bright_f[p];   break;
                case 4: param = contrast_f[p]; break;
                case 5: param = 0.05f;         break;   // slight noise scale
                case 6: param = slight_f[p];   break;
                default: break;
            }
            g_meta[p] = make_float4(__int_as_float(code), param, mpp, 0.0f);
        }
    }
}

// ---------------------------------------------------------------------------
// Kernel B: apply per-patch action. One thread = one float4 (4 pixels).
// Patch-major thread mapping keeps code warp-uniform. All single-use traffic
// (img re-read, noise, out) uses streaming cache policy.
// ---------------------------------------------------------------------------
__global__ void __launch_bounds__(256) apply_kernel(
    const float4* __restrict__ img,
    const float4* __restrict__ noise,
    float4*       __restrict__ out)
{
    const int t = blockIdx.x * blockDim.x + threadIdx.x;  // 0 .. 8388607
    const int fq   = t & 63;            // float4 slot within patch
    int rest       = t >> 6;
    const int pw   = rest & 63;
    const int ph   = (rest >> 6) & 63;
    const int b    = rest >> 12;
    const int row  = fq >> 2;
    const int c4   = fq & 3;
    const int y    = (ph << 4) + row;
    const int x0   = (pw << 4) + (c4 << 2);
    const int pix  = (b << 20) + (y << 10) + x0;
    const int fi   = pix >> 2;

    const float4 m = g_meta[(ph << 6) + pw];
    const int code = __float_as_int(m.x);

    float4 o;
    if (code == 0) {                          // identity (~20% of patches)
        o = __ldcs(&img[fi]);
    } else if (code == 1 || code == 5) {      // noise / slight noise
        const float4 v = __ldcs(&img[fi]);
        const float4 n = __ldcs(&noise[fi]);
        const float  s = m.y;
        o.x = clipf(fmaf(s, n.x, v.x));
        o.y = clipf(fmaf(s, n.y, v.y));
        o.z = clipf(fmaf(s, n.z, v.z));
        o.w = clipf(fmaf(s, n.w, v.w));
    } else if (code == 2) {                   // 3x3 avg blur, zero-padded per patch
        float4 acc = make_float4(0.f, 0.f, 0.f, 0.f);
        const float* imgf = (const float*)img;
        #pragma unroll
        for (int dr = -1; dr <= 1; dr++) {
            const int r = row + dr;
            if (r < 0 || r > 15) continue;    // zero padding confined to patch
            const int base = (b << 20) + ((((ph << 4) + r)) << 10) + x0;
            const float4 vv = __ldg(&img[base >> 2]);   // re-used across dr by L1
            const float l  = (c4 > 0) ? __ldg(imgf + base - 1) : 0.0f;
            const float rt = (c4 < 3) ? __ldg(imgf + base + 4) : 0.0f;
            acc.x += l    + vv.x + vv.y;
            acc.y += vv.x + vv.y + vv.z;
            acc.z += vv.y + vv.z + vv.w;
            acc.w += vv.z + vv.w + rt;
        }
        const float inv9 = 1.0f / 9.0f;       // reference does NOT clip blur
        o.x = acc.x * inv9; o.y = acc.y * inv9;
        o.z = acc.z * inv9; o.w = acc.w * inv9;
    } else if (code == 3 || code == 6) {      // brightness / slight brightness
        const float4 v = __ldcs(&img[fi]);
        const float  f = m.y;
        o.x = clipf(v.x * f); o.y = clipf(v.y * f);
        o.z = clipf(v.z * f); o.w = clipf(v.w * f);
    } else if (code == 4) {                   // contrast about batch-patch mean
        const float4 v  = __ldcs(&img[fi]);
        const float  cf = m.y;
        const float  mp = m.z;
        o.x = clipf(fmaf(v.x - mp, cf, mp));
        o.y = clipf(fmaf(v.y - mp, cf, mp));
        o.z = clipf(fmaf(v.z - mp, cf, mp));
        o.w = clipf(fmaf(v.w - mp, cf, mp));
    } else {                                  // 7: drop
        o = make_float4(0.f, 0.f, 0.f, 0.f);
    }
    __stcs(&out[fi], o);                      // streaming store: don't evict img
}

extern "C" void kernel_launch(void* const* d_in, const int* in_sizes, int n_in,
                              void* d_out, int out_size)
{
    const float4* img   = (const float4*)d_in[0];
    const float4* noise = (const float4*)d_in[1];

    stats_kernel<<<NPATCH, 256>>>(
        img,
        (const float*)d_in[2],   // r_strong
        (const float*)d_in[3],   // r_drop
        (const float*)d_in[4],   // r_else
        (const float*)d_in[5],   // bright_f
        (const float*)d_in[6],   // contrast_f
        (const float*)d_in[7],   // slight_f
        (const int*)d_in[8],     // aug_choice
        (const int*)d_in[9]);    // slight_choice

    // 32 * 1024 * 1024 / 4 float4s = 8388608 threads
    apply_kernel<<<8388608 / 256, 256>>>(img, noise, (float4*)d_out);
}

// round 3
// speedup vs baseline: 1.1810x; 1.1810x over previous
#include <cuda_runtime.h>

// QualityAwarePatchAugment — GB300 sm_103a — R3: single fused kernel.
// B=32, C=1, H=W=1024, PS=16 -> 64x64 = 4096 patches.
//
// The cross-batch dependency (q = batch-mean quality, m_pp = batch+pixel mean)
// is per-patch only: 32 batches x 256 px = 32 KB -> fits in one block's smem.
// One block per patch does stats AND apply, so img is read from DRAM exactly
// once (R1/R2 read it twice; L2 reuse across launches proved impossible:
// reuse distance ~= capacity).

__device__ __forceinline__ float clipf(float v) {
    return fminf(fmaxf(v, 0.0f), 1.0f);
}

__global__ void __launch_bounds__(256) fused_kernel(
    const float4* __restrict__ img,
    const float4* __restrict__ noise,
    float4*       __restrict__ out,
    const float*  __restrict__ r_strong,
    const float*  __restrict__ r_drop,
    const float*  __restrict__ r_else,
    const float*  __restrict__ bright_f,
    const float*  __restrict__ contrast_f,
    const float*  __restrict__ slight_f,
    const int*    __restrict__ aug_choice,
    const int*    __restrict__ slight_choice)
{
    __shared__ float sm[32 * 256];          // [batch][row][col], 32 KB
    __shared__ float sh_s[32], sh_s2[32];
    __shared__ float4 s_meta;               // x=code bits, y=param, z=m_pp

    const int p  = blockIdx.x;              // patch index = ph*64 + pw
    const int ph = p >> 6;
    const int pw = p & 63;
    const int t  = threadIdx.x;
    const int b  = t >> 3;                  // batch 0..31
    const int l8 = t & 7;                   // 8 threads per batch

    // float4 base index of (batch b, patch row 0): row stride = 256 float4
    const int f4base = (b << 18) + (ph << 12) + (pw << 2);
    float* const sm_b = sm + (b << 8);

    // ---- Phase 1: load 8 float4s -> registers + smem, accumulate stats ----
    float4 v[8];
    float s = 0.0f, s2 = 0.0f;
    #pragma unroll
    for (int k = 0; k < 8; k++) {
        const int fi  = l8 + (k << 3);      // float4 slot in patch, 0..63
        const int row = fi >> 2;
        const int c4  = fi & 3;
        v[k] = img[f4base + (row << 8) + c4];
        s  += v[k].x + v[k].y + v[k].z + v[k].w;
        s2 += v[k].x * v[k].x + v[k].y * v[k].y
            + v[k].z * v[k].z + v[k].w * v[k].w;
        *reinterpret_cast<float4*>(sm_b + (row << 4) + (c4 << 2)) = v[k];
    }
    #pragma unroll
    for (int off = 4; off; off >>= 1) {
        s  += __shfl_down_sync(0xffffffffu, s,  off, 8);
        s2 += __shfl_down_sync(0xffffffffu, s2, off, 8);
    }
    if (l8 == 0) { sh_s[b] = s; sh_s2[b] = s2; }
    __syncthreads();

    // ---- Phase 2: warp 0 folds batches -> code / param / m_pp ----
    if (t < 32) {
        const float bs  = sh_s[t];
        const float bs2 = sh_s2[t];
        const float mean = bs * (1.0f / 256.0f);
        float var = (bs2 - bs * bs * (1.0f / 256.0f)) * (1.0f / 255.0f); // ddof=1
        var = fmaxf(var, 0.0f);
        const float sd   = sqrtf(var);
        const float iq   = 1.0f - 2.0f * fabsf(mean - 0.5f);
        const float qual = (sd + iq + var) * (1.0f / 3.0f);

        float qs  = qual;
        float tot = bs;
        #pragma unroll
        for (int off = 16; off; off >>= 1) {
            qs  += __shfl_down_sync(0xffffffffu, qs,  off);
            tot += __shfl_down_sync(0xffffffffu, tot, off);
        }
        if (t == 0) {
            const float q   = qs  * (1.0f / 32.0f);
            const float mpp = tot * (1.0f / 8192.0f);   // 32 * 256 px

            const bool low    = q < 0.7f;
            const bool strong = low && (r_strong[p] < 0.8f);
            const bool drop   = low && (q < 0.3f) && (r_drop[p] < 0.1f);
            const bool els    = (!low) && (r_else[p] < 0.3f);

            int code = 0;
            if (strong) code = aug_choice[p] + 1;       // 1..4
            if (els)    code = slight_choice[p] + 5;    // 5..6
            if (drop)   code = 7;

            float param = 0.0f;
            switch (code) {
                case 1: param = 0.1f;          break;
                case 3: param = bright_f[p];   break;
                case 4: param = contrast_f[p]; break;
                case 5: param = 0.05f;         break;
                case 6: param = slight_f[p];   break;
                default: break;
            }
            s_meta = make_float4(__int_as_float(code), param, mpp, 0.0f);
        }
    }
    __syncthreads();

    const int   code  = __float_as_int(s_meta.x);
    const float param = s_meta.y;
    const float mpp   = s_meta.z;

    // ---- Phase 3: apply (block-uniform branch; pointwise ops from regs) ----
    if (code == 0) {                              // identity (~20%)
        #pragma unroll
        for (int k = 0; k < 8; k++) {
            const int fi = l8 + (k << 3);
            out[f4base + ((fi >> 2) << 8) + (fi & 3)] = v[k];
        }
    } else if (code == 1 || code == 5) {          // noise / slight noise
        #pragma unroll
        for (int k = 0; k < 8; k++) {
            const int fi = l8 + (k << 3);
            const int gi = f4base + ((fi >> 2) << 8) + (fi & 3);
            const float4 n = __ldcs(&noise[gi]);
            float4 o;
            o.x = clipf(fmaf(param, n.x, v[k].x));
            o.y = clipf(fmaf(param, n.y, v[k].y));
            o.z = clipf(fmaf(param, n.z, v[k].z));
            o.w = clipf(fmaf(param, n.w, v[k].w));
            out[gi] = o;
        }
    } else if (code == 2) {                       // 3x3 avg blur, zero-padded
        const float inv9 = 1.0f / 9.0f;
        #pragma unroll
        for (int k = 0; k < 8; k++) {
            const int fi  = l8 + (k << 3);
            const int row = fi >> 2;
            const int c0  = (fi & 3) << 2;        // first col of this float4
            float a0 = 0.f, a1 = 0.f, a2 = 0.f, a3 = 0.f;
            #pragma unroll
            for (int dr = -1; dr <= 1; dr++) {
                const int r = row + dr;
                if (r < 0 || r > 15) continue;
                const float* rp = sm_b + (r << 4);
                const float lft = (c0 > 0)  ? rp[c0 - 1] : 0.0f;
                const float rgt = (c0 < 12) ? rp[c0 + 4] : 0.0f;
                const float m0 = rp[c0], m1 = rp[c0 + 1];
                const float m2 = rp[c0 + 2], m3 = rp[c0 + 3];
                a0 += lft + m0 + m1;
                a1 += m0 + m1 + m2;
                a2 += m1 + m2 + m3;
                a3 += m2 + m3 + rgt;
            }
            float4 o = make_float4(a0 * inv9, a1 * inv9, a2 * inv9, a3 * inv9);
            out[f4base + (row << 8) + ((fi & 3))] = o;
        }
    } else if (code == 3 || code == 6) {          // brightness variants
        #pragma unroll
        for (int k = 0; k < 8; k++) {
            const int fi = l8 + (k << 3);
            float4 o;
            o.x = clipf(v[k].x * param);
            o.y = clipf(v[k].y * param);
            o.z = clipf(v[k].z * param);
            o.w = clipf(v[k].w * param);
            out[f4base + ((fi >> 2) << 8) + (fi & 3)] = o;
        }
    } else if (code == 4) {                       // contrast about m_pp
        #pragma unroll
        for (int k = 0; k < 8; k++) {
            const int fi = l8 + (k << 3);
            float4 o;
            o.x = clipf(fmaf(v[k].x - mpp, param, mpp));
            o.y = clipf(fmaf(v[k].y - mpp, param, mpp));
            o.z = clipf(fmaf(v[k].z - mpp, param, mpp));
            o.w = clipf(fmaf(v[k].w - mpp, param, mpp));
            out[f4base + ((fi >> 2) << 8) + (fi & 3)] = o;
        }
    } else {                                      // 7: drop -> zeros
        const float4 z = make_float4(0.f, 0.f, 0.f, 0.f);
        #pragma unroll
        for (int k = 0; k < 8; k++) {
            const int fi = l8 + (k << 3);
            out[f4base + ((fi >> 2) << 8) + (fi & 3)] = z;
        }
    }
}

extern "C" void kernel_launch(void* const* d_in, const int* in_sizes, int n_in,
                              void* d_out, int out_size)
{
    fused_kernel<<<4096, 256>>>(
        (const float4*)d_in[0],   // img
        (const float4*)d_in[1],   // noise
        (float4*)d_out,
        (const float*)d_in[2],    // r_strong
        (const float*)d_in[3],    // r_drop
        (const float*)d_in[4],    // r_else
        (const float*)d_in[5],    // bright_f
        (const float*)d_in[6],    // contrast_f
        (const float*)d_in[7],    // slight_f
        (const int*)d_in[8],      // aug_choice
        (const int*)d_in[9]);     // slight_choice
}